// round 1
// baseline (speedup 1.0000x reference)
#include <cuda_runtime.h>
#include <cstdint>
#include <math.h>

// Problem constants (fixed by the dataset problem)
#define BATCH 16
#define NPTS  6890
#define MPTS  6890

#define TPB     256          // threads per block
#define RB      4            // v1 points per thread (register blocking)
#define ROWS_PB (TPB * RB)   // 1024 rows per block
#define TILE_J  256          // v2 points staged in smem per iteration
#define MSPLIT  4            // split M across blocks for parallelism

__device__ unsigned int g_min_bits;   // bit pattern of min squared distance (nonneg float)

__global__ void init_kernel() {
    g_min_bits = 0x7F800000u;  // +inf
}

__global__ __launch_bounds__(TPB) void pairmin_kernel(
    const float* __restrict__ v1,
    const float* __restrict__ v2)
{
    const int b    = blockIdx.y;
    const int row0 = blockIdx.x * ROWS_PB + threadIdx.x;
    // M range for this block
    const int jchunk = (MPTS + MSPLIT - 1) / MSPLIT;
    const int j0 = blockIdx.z * jchunk;
    const int j1 = min(j0 + jchunk, MPTS);

    __shared__ float sx[TILE_J], sy[TILE_J], sz[TILE_J];

    float x[RB], y[RB], z[RB], m[RB];
#pragma unroll
    for (int r = 0; r < RB; r++) {
        int n = row0 + r * TPB;
        if (n < NPTS) {
            const float* p = v1 + ((size_t)b * NPTS + n) * 3;
            x[r] = p[0]; y[r] = p[1]; z[r] = p[2];
        } else {
            // sentinel: huge coords -> sq = inf, never the min
            x[r] = 1e30f; y[r] = 1e30f; z[r] = 1e30f;
        }
        m[r] = INFINITY;
    }

    for (int jt = j0; jt < j1; jt += TILE_J) {
        __syncthreads();
        {
            int t = threadIdx.x;   // TPB == TILE_J
            int j = jt + t;
            if (j < j1) {
                const float* q = v2 + ((size_t)b * MPTS + j) * 3;
                sx[t] = q[0]; sy[t] = q[1]; sz[t] = q[2];
            } else {
                sx[t] = -1e30f; sy[t] = -1e30f; sz[t] = -1e30f;
            }
        }
        __syncthreads();

#pragma unroll 4
        for (int t = 0; t < TILE_J; t++) {
            const float bx = sx[t], by = sy[t], bz = sz[t];
#pragma unroll
            for (int r = 0; r < RB; r++) {
                float dx = x[r] - bx;
                float dy = y[r] - by;
                float dz = z[r] - bz;
                float sq = fmaf(dz, dz, fmaf(dy, dy, dx * dx));
                m[r] = fminf(m[r], sq);
            }
        }
    }

    // reduce RB partial mins, then warp reduce, then one atomic per warp
    float v = fminf(fminf(m[0], m[1]), fminf(m[2], m[3]));
#pragma unroll
    for (int o = 16; o > 0; o >>= 1)
        v = fminf(v, __shfl_xor_sync(0xFFFFFFFFu, v, o));
    if ((threadIdx.x & 31) == 0)
        atomicMin(&g_min_bits, __float_as_uint(v));
}

__global__ void finish_kernel(float* __restrict__ out) {
    out[0] = sqrtf(fmaxf(__uint_as_float(g_min_bits), 0.0f));
}

extern "C" void kernel_launch(void* const* d_in, const int* in_sizes, int n_in,
                              void* d_out, int out_size)
{
    const float* v1 = (const float*)d_in[0];
    const float* v2 = (const float*)d_in[1];
    float* out = (float*)d_out;

    init_kernel<<<1, 1>>>();

    dim3 grid((NPTS + ROWS_PB - 1) / ROWS_PB, BATCH, MSPLIT);
    pairmin_kernel<<<grid, TPB>>>(v1, v2);

    finish_kernel<<<1, 1>>>(out);
}

// round 2
// speedup vs baseline: 1.6130x; 1.6130x over previous
#include <cuda_runtime.h>
#include <cstdint>
#include <math.h>

// Problem constants (fixed by the dataset problem)
#define BATCH 16
#define NPTS  6890
#define MPTS  6890

#define TPB     256          // threads per block
#define RB      4            // v1 points per thread (register blocking)
#define ROWS_PB (TPB * RB)   // 1024 rows per block
#define TILE_J  256          // v2 points staged in smem per iteration
#define NPAIRJ  (TILE_J / 2)
#define MSPLIT  4            // split M across blocks for parallelism

__device__ unsigned int g_min_bits;   // bit pattern of min squared distance (nonneg float)

__global__ void init_kernel() {
    g_min_bits = 0x7F800000u;  // +inf
}

// 64-bit packed-f32x2 helpers
__device__ __forceinline__ unsigned long long pack2(float lo, float hi) {
    unsigned long long v;
    asm("mov.b64 %0, {%1, %2};" : "=l"(v) : "f"(lo), "f"(hi));
    return v;
}
__device__ __forceinline__ void unpack2(unsigned long long v, float& lo, float& hi) {
    asm("mov.b64 {%0, %1}, %2;" : "=f"(lo), "=f"(hi) : "l"(v));
}
__device__ __forceinline__ unsigned long long fma2(unsigned long long a,
                                                   unsigned long long b,
                                                   unsigned long long c) {
    unsigned long long d;
    asm("fma.rn.f32x2 %0, %1, %2, %3;" : "=l"(d) : "l"(a), "l"(b), "l"(c));
    return d;
}

__global__ __launch_bounds__(TPB) void pairmin_kernel(
    const float* __restrict__ v1,
    const float* __restrict__ v2)
{
    const int b    = blockIdx.y;
    const int row0 = blockIdx.x * ROWS_PB + threadIdx.x;
    const int jchunk = (MPTS + MSPLIT - 1) / MSPLIT;
    const int j0 = blockIdx.z * jchunk;
    const int j1 = min(j0 + jchunk, MPTS);

    // packed column tiles: s_bxy[i] = (x0, x1, y0, y1), s_bzh[i] = (z0, z1, h0, h1)
    __shared__ float4 s_bxy[NPAIRJ];
    __shared__ float4 s_bzh[NPAIRJ];

    // per-row constants: c* = -2 * coord (broadcast-packed), xx = ||p||^2
    unsigned long long cx2[RB], cy2[RB], cz2[RB];
    float xx[RB], m0[RB], m1[RB];
#pragma unroll
    for (int r = 0; r < RB; r++) {
        int n = row0 + r * TPB;
        float x = 0.f, y = 0.f, z = 0.f;
        if (n < NPTS) {
            const float* p = v1 + ((size_t)b * NPTS + n) * 3;
            x = p[0]; y = p[1]; z = p[2];
            xx[r] = x * x + y * y + z * z;
        } else {
            xx[r] = INFINITY;   // sentinel row: inf + anything finite = inf
        }
        cx2[r] = pack2(-2.f * x, -2.f * x);
        cy2[r] = pack2(-2.f * y, -2.f * y);
        cz2[r] = pack2(-2.f * z, -2.f * z);
        m0[r] = INFINITY;
        m1[r] = INFINITY;
    }

    for (int jt = j0; jt < j1; jt += TILE_J) {
        __syncthreads();
        if (threadIdx.x < NPAIRJ) {
            int jp = jt + 2 * threadIdx.x;
            float x0 = 0.f, y0 = 0.f, z0 = 0.f, h0 = INFINITY;
            float x1 = 0.f, y1 = 0.f, z1 = 0.f, h1 = INFINITY;
            if (jp < j1) {
                const float* q = v2 + ((size_t)b * MPTS + jp) * 3;
                x0 = q[0]; y0 = q[1]; z0 = q[2];
                h0 = x0 * x0 + y0 * y0 + z0 * z0;
            }
            if (jp + 1 < j1) {
                const float* q = v2 + ((size_t)b * MPTS + jp + 1) * 3;
                x1 = q[0]; y1 = q[1]; z1 = q[2];
                h1 = x1 * x1 + y1 * y1 + z1 * z1;
            }
            s_bxy[threadIdx.x] = make_float4(x0, x1, y0, y1);
            s_bzh[threadIdx.x] = make_float4(z0, z1, h0, h1);
        }
        __syncthreads();

#pragma unroll 4
        for (int i = 0; i < NPAIRJ; i++) {
            float4 bxy = s_bxy[i];
            float4 bzh = s_bzh[i];
            unsigned long long bx2 = pack2(bxy.x, bxy.y);
            unsigned long long by2 = pack2(bxy.z, bxy.w);
            unsigned long long bz2 = pack2(bzh.x, bzh.y);
            unsigned long long h2  = pack2(bzh.z, bzh.w);
#pragma unroll
            for (int r = 0; r < RB; r++) {
                // d = yy - 2*(x*bx + y*by + z*bz), two j-points per packed op
                unsigned long long d2 = fma2(cx2[r], bx2, h2);
                d2 = fma2(cy2[r], by2, d2);
                d2 = fma2(cz2[r], bz2, d2);
                float d0, d1;
                unpack2(d2, d0, d1);
                m0[r] = fminf(m0[r], d0);
                m1[r] = fminf(m1[r], d1);
            }
        }
    }

    // combine: sq_min for row r = xx[r] + min_t d ; clamp negatives (ref semantics)
    float v = INFINITY;
#pragma unroll
    for (int r = 0; r < RB; r++)
        v = fminf(v, xx[r] + fminf(m0[r], m1[r]));
    v = fmaxf(v, 0.0f);

#pragma unroll
    for (int o = 16; o > 0; o >>= 1)
        v = fminf(v, __shfl_xor_sync(0xFFFFFFFFu, v, o));
    if ((threadIdx.x & 31) == 0)
        atomicMin(&g_min_bits, __float_as_uint(v));
}

__global__ void finish_kernel(float* __restrict__ out) {
    out[0] = sqrtf(fmaxf(__uint_as_float(g_min_bits), 0.0f));
}

extern "C" void kernel_launch(void* const* d_in, const int* in_sizes, int n_in,
                              void* d_out, int out_size)
{
    const float* v1 = (const float*)d_in[0];
    const float* v2 = (const float*)d_in[1];
    float* out = (float*)d_out;

    init_kernel<<<1, 1>>>();

    dim3 grid((NPTS + ROWS_PB - 1) / ROWS_PB, BATCH, MSPLIT);
    pairmin_kernel<<<grid, TPB>>>(v1, v2);

    finish_kernel<<<1, 1>>>(out);
}

// round 4
// speedup vs baseline: 5.8855x; 3.6487x over previous
#include <cuda_runtime.h>
#include <cstdint>
#include <math.h>

// Problem constants (fixed by the dataset problem)
#define BATCH  16
#define NPTS   6890           // N == M == 6890
#define SORT_N 8192           // padded size (power of 2)
#define NBUCK  2048           // x-buckets for counting sort
#define BSCALE 128.0f         // buckets per unit x  (range [-8, 8) -> 2048 buckets)
#define BOFF   8.0f

#define BBLK   256
#define GRID_X 27             // 27 * 256 = 6912 >= 6890

// ---- device state (static globals; no allocation) ----
__device__ float4 g_p1[BATCH][SORT_N];          // sorted v1: (x, y, z, ||p||^2)
__device__ float4 g_p2[BATCH][SORT_N];          // sorted v2: (x, y, z, ||q||^2)
__device__ int    g_bstart[BATCH][NBUCK + 1];   // v2 bucket start offsets
__device__ int    g_bound_i;                    // float bits of upper-bound sq (as signed int)
__device__ int    g_min_i;                      // float bits of running min sq
__device__ int    g_arr;                        // arrival counter (zero-init, self-resetting)

__device__ __forceinline__ int bucket_of(float x) {
    // monotone non-decreasing map (trunc + clamp are monotone)
    int b = (int)((x + BOFF) * BSCALE);
    return min(max(b, 0), NBUCK - 1);
}

// ============================================================
// Kernel 1: counting-sort both clouds of every batch by x-bucket
// ============================================================
__global__ __launch_bounds__(1024) void build_kernel(
    const float* __restrict__ v1, const float* __restrict__ v2)
{
    __shared__ int hist[NBUCK];
    __shared__ int warpsum[32];

    const int b     = blockIdx.x >> 1;
    const int cloud = blockIdx.x & 1;
    const float* src = cloud ? v2 : v1;
    const float  big = cloud ? 2e30f : 1e30f;   // distinct sentinels so pad-vs-pad dist = inf
    const int tid = threadIdx.x;

    for (int i = tid; i < NBUCK; i += 1024) hist[i] = 0;
    __syncthreads();

    // pass 1: histogram
    for (int i = tid; i < SORT_N; i += 1024) {
        float x = (i < NPTS) ? src[((size_t)b * NPTS + i) * 3] : big;
        atomicAdd(&hist[bucket_of(x)], 1);
    }
    __syncthreads();

    // scan (2048 buckets, 2 per thread) -> exclusive offsets
    int a0 = hist[2 * tid], a1 = hist[2 * tid + 1];
    int s = a0 + a1;
    int lane = tid & 31, wid = tid >> 5;
    int v = s;
#pragma unroll
    for (int o = 1; o < 32; o <<= 1) {
        int t = __shfl_up_sync(0xFFFFFFFFu, v, o);
        if (lane >= o) v += t;
    }
    if (lane == 31) warpsum[wid] = v;
    __syncthreads();
    if (wid == 0) {
        int w = warpsum[lane];
#pragma unroll
        for (int o = 1; o < 32; o <<= 1) {
            int t = __shfl_up_sync(0xFFFFFFFFu, w, o);
            if (lane >= o) w += t;
        }
        warpsum[lane] = w;
    }
    __syncthreads();
    int excl = v - s + ((wid > 0) ? warpsum[wid - 1] : 0);
    __syncthreads();                 // everyone done reading hist as counts
    hist[2 * tid]     = excl;
    hist[2 * tid + 1] = excl + a0;
    if (cloud) {
        g_bstart[b][2 * tid]     = excl;
        g_bstart[b][2 * tid + 1] = excl + a0;
        if (tid == 0) g_bstart[b][NBUCK] = SORT_N;
    }
    __syncthreads();

    // pass 2: scatter sorted float4 (x, y, z, ||.||^2)
    float4 (*dst)[SORT_N] = cloud ? g_p2 : g_p1;
    for (int i = tid; i < SORT_N; i += 1024) {
        float4 p;
        if (i < NPTS) {
            const float* q = src + ((size_t)b * NPTS + i) * 3;
            float x = q[0], y = q[1], z = q[2];
            p = make_float4(x, y, z, fmaf(z, z, fmaf(y, y, x * x)));
        } else {
            p = make_float4(big, big, big, INFINITY);
        }
        int pos = atomicAdd(&hist[bucket_of(p.x)], 1);
        dst[b][pos] = p;
    }

    if (blockIdx.x == 0 && tid == 0) {
        g_bound_i = 0x7F800000;     // +inf bits
        g_min_i   = 0x7F800000;
    }
}

// ============================================================
// Kernel 2: cheap upper bound U_sq (j-stride-64 genuine pairs)
// ============================================================
__global__ __launch_bounds__(BBLK) void bound_kernel()
{
    const int b = blockIdx.y;
    const int i = blockIdx.x * BBLK + threadIdx.x;
    float4 p = g_p1[b][i];
    float nx = -2.f * p.x, ny = -2.f * p.y, nz = -2.f * p.z;
    int phase = (i >> 5) & 63;                 // warp-uniform -> broadcast loads
    float m = INFINITY;
    for (int j = phase; j < NPTS; j += 64) {
        float4 q = g_p2[b][j];
        float d = fmaf(nx, q.x, q.w);
        d = fmaf(ny, q.y, d);
        d = fmaf(nz, q.z, d);
        m = fminf(m, d);                       // fminf drops NaN operands
    }
    float v = p.w + m;                         // sq = ||p||^2 + (||q||^2 - 2 p.q)
#pragma unroll
    for (int o = 16; o; o >>= 1) v = fminf(v, __shfl_xor_sync(0xFFFFFFFFu, v, o));
    __shared__ float sm[BBLK / 32];
    if ((threadIdx.x & 31) == 0) sm[threadIdx.x >> 5] = v;
    __syncthreads();
    if (threadIdx.x == 0) {
        float t = sm[0];
#pragma unroll
        for (int w = 1; w < BBLK / 32; w++) t = fminf(t, sm[w]);
        atomicMin(&g_bound_i, __float_as_int(t));   // signed-int order OK (see clamp)
    }
}

// ============================================================
// Kernel 3: pruned exact pass + final reduce + output
// ============================================================
__global__ __launch_bounds__(BBLK) void prune_kernel(float* __restrict__ out)
{
    const int b = blockIdx.y;
    const int i = blockIdx.x * BBLK + threadIdx.x;
    float4 p = g_p1[b][i];
    float nx = -2.f * p.x, ny = -2.f * p.y, nz = -2.f * p.z;

    float usq = __int_as_float(g_bound_i);
    // slack: fp32 cancellation error of dot-form sq + sqrt rounding
    float U = sqrtf(fmaxf(usq, 0.f) + 5e-5f) * 1.0002f;

    int lo = 0, hi = 0;
    if (p.w < INFINITY) {                      // skip pad rows entirely
        lo = g_bstart[b][bucket_of(p.x - U)];
        hi = g_bstart[b][bucket_of(p.x + U) + 1];
    }

    float m = INFINITY;
    for (int t = lo; t < hi; t++) {
        float4 q = g_p2[b][t];
        float d = fmaf(nx, q.x, q.w);
        d = fmaf(ny, q.y, d);
        d = fmaf(nz, q.z, d);
        m = fminf(m, d);
    }
    float v = p.w + m;
#pragma unroll
    for (int o = 16; o; o >>= 1) v = fminf(v, __shfl_xor_sync(0xFFFFFFFFu, v, o));
    __shared__ float sm[BBLK / 32];
    if ((threadIdx.x & 31) == 0) sm[threadIdx.x >> 5] = v;
    __syncthreads();
    if (threadIdx.x == 0) {
        float t = sm[0];
#pragma unroll
        for (int w = 1; w < BBLK / 32; w++) t = fminf(t, sm[w]);
        // NaN (empty pad rows) -> bits 0x7FC00000 > +inf bits: never wins. Fine.
        atomicMin(&g_min_i, __float_as_int(t));
        __threadfence();
        int old = atomicAdd(&g_arr, 1);
        if (old == (int)(gridDim.x * gridDim.y) - 1) {
            int mb = atomicAdd(&g_min_i, 0);   // coherent read
            out[0] = sqrtf(fmaxf(__int_as_float(mb), 0.f));
            g_arr = 0;                          // reset for next replay
        }
    }
}

extern "C" void kernel_launch(void* const* d_in, const int* in_sizes, int n_in,
                              void* d_out, int out_size)
{
    const float* v1 = (const float*)d_in[0];
    const float* v2 = (const float*)d_in[1];
    float* out = (float*)d_out;

    build_kernel<<<BATCH * 2, 1024>>>(v1, v2);

    dim3 grid(GRID_X, BATCH);
    bound_kernel<<<grid, BBLK>>>();
    prune_kernel<<<grid, BBLK>>>(out);
}